// round 5
// baseline (speedup 1.0000x reference)
#include <cuda_runtime.h>

#define MAXROWS 8192
#define NT      512
#define NW      (NT / 32)           // 16 warps
#define SLOTS   16                  // per-thread candidate slots (interleaved layout)

__device__ float g_rowloss[MAXROWS];

__device__ __forceinline__ float warpReduceSum(float v) {
#pragma unroll
    for (int o = 16; o; o >>= 1) v += __shfl_down_sync(0xffffffffu, v, o);
    return v;
}

// Returns the block sum to ALL threads (each thread sums the NW warp partials
// in the same fixed order -> deterministic and uniform).
__device__ __forceinline__ float blockReduceSumAll(float v, float* sbuf) {
    int lane = threadIdx.x & 31, warp = threadIdx.x >> 5;
    v = warpReduceSum(v);
    __syncthreads();                     // protect sbuf from previous round
    if (lane == 0) sbuf[warp] = v;
    __syncthreads();
    float s = 0.f;
#pragma unroll
    for (int w = 0; w < NW; w++) s += sbuf[w];
    return s;
}

// Robust target load: auto-detect int32 vs int64 storage (int64 -> odd words zero).
__device__ __forceinline__ int load_target(const void* tgt, int row, int n, int d) {
    const int* t32 = (const int*)tgt;
    int lim = (n < 32) ? n : 32;
    bool is64 = true;
    for (int i = 0; i < lim; i++) is64 = is64 && (t32[2 * i + 1] == 0);
    long long v = is64 ? ((const long long*)tgt)[row] : (long long)t32[row];
    int t = (int)v;
    if (t < 0 || t >= d) t = 0;
    return t;
}

// Branchless keep of one raw input value (predicated STS, no divergence arm).
#define KEEP1(val)                                                   \
    do {                                                             \
        int _a = ((c < SLOTS ? c : SLOTS - 1) * NT) + tid;           \
        bool _k = (val) > th;                                        \
        if (_k) cand[_a] = (val);                                    \
        c += _k ? 1 : 0;                                             \
    } while (0)

#define KEEP4(v) do { KEEP1((v).x); KEEP1((v).y); KEEP1((v).z); KEEP1((v).w); } while (0)

#define MAX4(v) fmaxf(fmaxf((v).x, (v).y), fmaxf((v).z, (v).w))

__global__ __launch_bounds__(NT) void tsallis_kernel(const float* __restrict__ in,
                                                     const void* __restrict__ tgt,
                                                     int d, int n) {
    int row  = blockIdx.x;
    int tid  = threadIdx.x;
    int lane = tid & 31, warp = tid >> 5;
    const float* xr = in + (size_t)row * d;

    __shared__ float cand[SLOTS * NT];   // 32 KB; slot j of thread t at [j*NT + t]; raw input units
    __shared__ float sred[NW];
    __shared__ int   s_ovf;

    if (tid == 0) s_ovf = 0;
    __syncthreads();

    float cm = -3.4e38f;   // running max (input units); thread-local, warp-merged per chunk
    float th = 3.4e38f;    // keep threshold (input units); valid after first full chunk
    int   c  = 0;          // per-thread kept count

    if ((d & 3) == 0) {
        const float4* p4  = (const float4*)xr;
        int nf4 = d >> 2;
        int nfull = nf4 / NT;            // full rounds where all NT threads load
        int rem   = nf4 - nfull * NT;

        int k = 0;
        // ---- Main chunks: 5 unconditional batched LDG.128 per thread ----
        for (; k + 5 <= nfull; k += 5) {
            const float4 v0 = p4[(k + 0) * NT + tid];
            const float4 v1 = p4[(k + 1) * NT + tid];
            const float4 v2 = p4[(k + 2) * NT + tid];
            const float4 v3 = p4[(k + 3) * NT + tid];
            const float4 v4 = p4[(k + 4) * NT + tid];
            float lm = fmaxf(fmaxf(fmaxf(MAX4(v0), MAX4(v1)), fmaxf(MAX4(v2), MAX4(v3))), MAX4(v4));
            cm = fmaxf(cm, lm);
            float t2 = cm;
#pragma unroll
            for (int o = 16; o; o >>= 1) t2 = fmaxf(t2, __shfl_xor_sync(0xffffffffu, t2, o));
            cm = t2;
            th = cm - 2.0f;              // input units: x > max_in-2  <=>  X > maxX-1
            KEEP4(v0); KEEP4(v1); KEEP4(v2); KEEP4(v3); KEEP4(v4);
        }
        // ---- Leftover full rounds (<5, uniform): filter with last threshold ----
        for (; k < nfull; k++) {
            const float4 v = p4[k * NT + tid];
            cm = fmaxf(cm, MAX4(v));
            KEEP4(v);
        }
        // ---- Remainder (ragged) ----
        if (tid < rem) {
            const float4 v = p4[nfull * NT + tid];
            cm = fmaxf(cm, MAX4(v));
            KEEP4(v);
        }
        // If no full chunk ran, th was never valid -> slow path (tiny d only).
        if (nfull < 5 && tid == 0) atomicOr(&s_ovf, 1);
    } else {
        // Unusual shape: exact max only, force slow path.
        float m = -3.4e38f;
        for (int i = tid; i < d; i += NT) m = fmaxf(m, xr[i]);
        cm = m;
        if (tid == 0) atomicOr(&s_ovf, 1);
    }

    if (c > SLOTS) atomicOr(&s_ovf, 1);

    // ---- Exact block max -> maxX ----
#pragma unroll
    for (int o = 16; o; o >>= 1) cm = fmaxf(cm, __shfl_xor_sync(0xffffffffu, cm, o));
    if (lane == 0) sred[warp] = cm;
    __syncthreads();
    float bm = sred[0];
#pragma unroll
    for (int w = 1; w < NW; w++) bm = fmaxf(bm, sred[w]);
    bool  slow   = (s_ovf != 0);
    float maxX   = 0.5f * bm;
    float tau_lo = maxX - 1.0f;
    float tau_hi = maxX - (float)(1.0 / sqrt((double)d));   // maxX - (1/d)^(alpha-1)
    int   myc    = slow ? 0 : c;

    // ---- f_lo ----
    float fl = 0.f;
    if (!slow) {
        for (int j = 0; j < myc; j++) {
            float t = fmaf(0.5f, cand[j * NT + tid], -tau_lo);
            if (t > 0.f) fl = fmaf(t, t, fl);
        }
    } else {
        for (int i = tid; i < d; i += NT) {
            float t = fmaxf(fmaf(0.5f, __ldg(xr + i), -tau_lo), 0.f);
            fl = fmaf(t, t, fl);
        }
    }
    float f_lo = blockReduceSumAll(fl, sred) - 1.0f;

    // ---- 15 bisection iterations ----
    float dm    = tau_hi - tau_lo;
    float tau_m = tau_lo;
#pragma unroll 1
    for (int it = 0; it < 15; it++) {
        dm *= 0.5f;
        tau_m = tau_lo + dm;
        float s = 0.f;
        if (!slow) {
            for (int j = 0; j < myc; j++) {
                float t = fmaxf(fmaf(0.5f, cand[j * NT + tid], -tau_m), 0.f);
                s = fmaf(t, t, s);
            }
        } else {
            for (int i = tid; i < d; i += NT) {
                float t = fmaxf(fmaf(0.5f, __ldg(xr + i), -tau_m), 0.f);
                s = fmaf(t, t, s);
            }
        }
        float fm = blockReduceSumAll(s, sred) - 1.0f;
        tau_lo = (fm * f_lo >= 0.f) ? tau_m : tau_lo;   // uniform across block
    }

    // ---- Finals at last tau_m: S3 = sum t^3, PX = sum p*X ----
    float s3 = 0.f, px = 0.f;
    if (!slow) {
        for (int j = 0; j < myc; j++) {
            float X = 0.5f * cand[j * NT + tid];
            float t = fmaxf(X - tau_m, 0.f);
            float p = t * t;
            s3 = fmaf(p, t, s3);
            px = fmaf(p, X, px);
        }
    } else {
        for (int i = tid; i < d; i += NT) {
            float X = 0.5f * __ldg(xr + i);
            float t = fmaxf(X - tau_m, 0.f);
            float p = t * t;
            s3 = fmaf(p, t, s3);
            px = fmaf(p, X, px);
        }
    }
    float S3 = blockReduceSumAll(s3, sred);
    float PX = blockReduceSumAll(px, sred);
    if (tid == 0) {
        int t = load_target(tgt, row, n, d);
        float xt = __ldg(xr + t);
        // loss = (1 - S3)/(alpha*(alpha-1)) + sum(p*input) - input[target]
        //      = (1 - S3)/0.75 + 2*PX - xt        (input = 2*X)
        g_rowloss[row] = (1.0f - S3) / 0.75f + 2.0f * PX - xt;
    }
}

// Deterministic mean over rows
__global__ __launch_bounds__(1024) void reduce_kernel(float* __restrict__ out, int n) {
    __shared__ float sbuf[32];
    float s = 0.f;
    int n4 = n >> 2;
    const float4* p4 = (const float4*)g_rowloss;
    for (int i = threadIdx.x; i < n4; i += 1024) {
        float4 v = p4[i];
        s += (v.x + v.y) + (v.z + v.w);
    }
    for (int i = (n4 << 2) + threadIdx.x; i < n; i += 1024) s += g_rowloss[i];
    s = warpReduceSum(s);
    if ((threadIdx.x & 31) == 0) sbuf[threadIdx.x >> 5] = s;
    __syncthreads();
    if (threadIdx.x < 32) {
        float x = sbuf[threadIdx.x];
        x = warpReduceSum(x);
        if (threadIdx.x == 0) out[0] = x / (float)n;
    }
}

extern "C" void kernel_launch(void* const* d_in, const int* in_sizes, int n_in,
                              void* d_out, int out_size) {
    // Pick logits vs targets by size: the big buffer is the [n, d] logits.
    int idx_in = 0, idx_tg = 1;
    if (n_in >= 2 && in_sizes[1] > in_sizes[0]) { idx_in = 1; idx_tg = 0; }
    const float* in  = (const float*)d_in[idx_in];
    const void*  tgt = d_in[idx_tg];

    int n = in_sizes[idx_tg];
    if (n <= 0) n = 1;
    int d = in_sizes[idx_in] / n;
    if (n > MAXROWS) n = MAXROWS;   // shapes fixed: 4096 x 32000

    tsallis_kernel<<<n, NT>>>(in, tgt, d, n);
    reduce_kernel<<<1, 1024>>>((float*)d_out, n);
}

// round 6
// speedup vs baseline: 2.6950x; 2.6950x over previous
#include <cuda_runtime.h>
#include <float.h>
#include <math.h>

#define MAXROWS 8192
#define NT      256
#define NW      (NT / 32)
#define SLOTF4  10          // per-thread kept-float4 slots in smem

__device__ float g_rowloss[MAXROWS];

__device__ __forceinline__ float warpMax(float v) {
#pragma unroll
    for (int o = 16; o; o >>= 1) v = fmaxf(v, __shfl_xor_sync(0xffffffffu, v, o));
    return v;
}
__device__ __forceinline__ float warpReduceSum(float v) {
#pragma unroll
    for (int o = 16; o; o >>= 1) v += __shfl_down_sync(0xffffffffu, v, o);
    return v;
}
// Block sum returned to ALL threads (fixed-order partial sum -> deterministic, uniform).
__device__ __forceinline__ float blockReduceSumAll(float v, float* sbuf) {
    int lane = threadIdx.x & 31, warp = threadIdx.x >> 5;
    v = warpReduceSum(v);
    __syncthreads();
    if (lane == 0) sbuf[warp] = v;
    __syncthreads();
    float s = 0.f;
#pragma unroll
    for (int w = 0; w < NW; w++) s += sbuf[w];
    return s;
}

// Robust target load: auto-detect int32 vs int64 storage (int64 -> odd words zero).
__device__ __forceinline__ int load_target(const void* tgt, int row, int n, int d) {
    const int* t32 = (const int*)tgt;
    int lim = (n < 32) ? n : 32;
    bool is64 = true;
    for (int i = 0; i < lim; i++) is64 = is64 && (t32[2 * i + 1] == 0);
    long long v = is64 ? ((const long long*)tgt)[row] : (long long)t32[row];
    int t = (int)v;
    if (t < 0 || t >= d) t = 0;
    return t;
}

// Slow path helper: full-row sum of relu(0.5*x - tau)^2
__device__ __forceinline__ float relu2_pass(const float* xr, int d, float tau, float* sbuf) {
    float s = 0.f;
    for (int i = threadIdx.x; i < d; i += NT) {
        float t = fmaxf(fmaf(0.5f, __ldg(xr + i), -tau), 0.f);
        s = fmaf(t, t, s);
    }
    return blockReduceSumAll(s, sbuf);
}

#define M4(v) fmaxf(fmaxf((v).x, (v).y), fmaxf((v).z, (v).w))

__global__ __launch_bounds__(NT) void tsallis_kernel(const float* __restrict__ in,
                                                     const void* __restrict__ tgt,
                                                     int d, int n) {
    int row  = blockIdx.x;
    int tid  = threadIdx.x;
    int lane = tid & 31, warp = tid >> 5;
    const float* xr = in + (size_t)row * d;
    const float4* p4 = (const float4*)xr;

    __shared__ float4 kf4[SLOTF4][NT];   // 40 KB kept-f4 buffer (thread-private columns)
    __shared__ float  swm[NW];
    __shared__ float  sred[NW];
    __shared__ int    sflag;

    if (tid == 0) sflag = 0;
    __syncthreads();

    int  nf4 = d >> 2;
    int  K   = nf4 / NT;                 // full rounds (31 for d=32000)
    int  rem = nf4 - K * NT;
    bool shape_ok = ((d & 3) == 0) && (K >= 1) && (K <= 31);

    unsigned hitmask = 0;
    float rm = -FLT_MAX;                 // running max, raw units
    float th = FLT_MAX;                  // stale keep threshold, raw units

    if (shape_ok) {
        int k = 0;
        // ---- main chunks: 8 unconditional batched LDG.128 per thread ----
        for (; k + 8 <= K; k += 8) {
            float4 v[8]; float m4[8];
#pragma unroll
            for (int u = 0; u < 8; u++) v[u] = p4[(k + u) * NT + tid];
#pragma unroll
            for (int u = 0; u < 8; u++) m4[u] = M4(v[u]);
            float cm = m4[0];
#pragma unroll
            for (int u = 1; u < 8; u++) cm = fmaxf(cm, m4[u]);
            rm = fmaxf(rm, cm);
            // block-level running max -> stale threshold (monotone <= final max)
            float wv = warpMax(rm);
            if (lane == 0) swm[warp] = wv;
            __syncthreads();
            float bm = swm[0];
#pragma unroll
            for (int w = 1; w < NW; w++) bm = fmaxf(bm, swm[w]);
            th = bm - 1.51f;
            __syncthreads();
#pragma unroll
            for (int u = 0; u < 8; u++)
                if (m4[u] > th) hitmask |= (1u << (k + u));
        }
        // ---- leftover full rounds (<8, uniform count) ----
        if (k < K) {
            int lk = K - k;
            float4 v[8]; float m4[8];
#pragma unroll
            for (int u = 0; u < 8; u++) if (u < lk) v[u] = p4[(k + u) * NT + tid];
#pragma unroll
            for (int u = 0; u < 8; u++) m4[u] = (u < lk) ? M4(v[u]) : -FLT_MAX;
            float cm = m4[0];
#pragma unroll
            for (int u = 1; u < 8; u++) cm = fmaxf(cm, m4[u]);
            rm = fmaxf(rm, cm);
            float wv = warpMax(rm);
            if (lane == 0) swm[warp] = wv;
            __syncthreads();
            float bm = swm[0];
#pragma unroll
            for (int w = 1; w < NW; w++) bm = fmaxf(bm, swm[w]);
            th = bm - 1.51f;
            __syncthreads();
#pragma unroll
            for (int u = 0; u < 8; u++)
                if (u < lk && m4[u] > th) hitmask |= (1u << (k + u));
        }
        // ---- remainder (ragged): bit K, tested vs last threshold (superset-safe) ----
        if (tid < rem) {
            float4 v = p4[K * NT + tid];
            float m4r = M4(v);
            rm = fmaxf(rm, m4r);
            if (m4r > th) hitmask |= (1u << K);
        }
    } else {
        float m = -FLT_MAX;
        for (int i = tid; i < d; i += NT) m = fmaxf(m, xr[i]);
        rm = m;
        if (tid == 0) sflag = 1;
    }

    // ---- exact block max ----
    {
        float wv = warpMax(rm);
        __syncthreads();
        if (lane == 0) swm[warp] = wv;
        __syncthreads();
    }
    float bmax = swm[0];
#pragma unroll
    for (int w = 1; w < NW; w++) bmax = fmaxf(bmax, swm[w]);

    float maxX    = 0.5f * bmax;
    float tau_lo0 = maxX - 1.0f;
    float tau_hi0 = maxX - (float)(1.0 / sqrt((double)d));   // maxX - (1/d)^(alpha-1)
    float guard   = maxX - 0.754f;      // kept-set covers X > maxX-0.755

    // ---- Phase 2: gather hit float4s into smem (thread-private columns) ----
    int cnt = 0;
    if (shape_ok) {
        unsigned hm = hitmask;
        while (hm) {
            int kb = __ffs(hm) - 1;
            hm &= hm - 1;
            if (cnt < SLOTF4) kf4[cnt][tid] = p4[kb * NT + tid];
            cnt++;
        }
        if (cnt > SLOTF4) atomicOr(&sflag, 1);
    }
    __syncthreads();
    bool slow = (sflag != 0);
    if (slow) cnt = 0;

    // ---- Fast bisection over kept f4s; mask = (f_m >= 0); guard each tau_m ----
    float dm    = tau_hi0 - tau_lo0;
    float tau_lo = tau_lo0;
    float tau_m = tau_lo0;
    int   gtrip = 0;
#pragma unroll 1
    for (int it = 0; it < 15; it++) {
        dm *= 0.5f;
        tau_m = tau_lo + dm;
        if (tau_m < guard) gtrip = 1;
        float s = 0.f;
        for (int j = 0; j < cnt; j++) {
            float4 v = kf4[j][tid];
            float t;
            t = fmaxf(fmaf(0.5f, v.x, -tau_m), 0.f); s = fmaf(t, t, s);
            t = fmaxf(fmaf(0.5f, v.y, -tau_m), 0.f); s = fmaf(t, t, s);
            t = fmaxf(fmaf(0.5f, v.z, -tau_m), 0.f); s = fmaf(t, t, s);
            t = fmaxf(fmaf(0.5f, v.w, -tau_m), 0.f); s = fmaf(t, t, s);
        }
        float fm = blockReduceSumAll(s, sred) - 1.0f;
        tau_lo = (fm >= 0.f) ? tau_m : tau_lo;    // uniform
    }

    bool slow2 = slow || (gtrip != 0);            // uniform across block
    float S3, PX, tau_f;

    if (!slow2) {
        tau_f = tau_m;
        float s3 = 0.f, px = 0.f;
        for (int j = 0; j < cnt; j++) {
            float4 v = kf4[j][tid];
            float X, t, p;
            X = 0.5f * v.x; t = fmaxf(X - tau_f, 0.f); p = t * t; s3 = fmaf(p, t, s3); px = fmaf(p, X, px);
            X = 0.5f * v.y; t = fmaxf(X - tau_f, 0.f); p = t * t; s3 = fmaf(p, t, s3); px = fmaf(p, X, px);
            X = 0.5f * v.z; t = fmaxf(X - tau_f, 0.f); p = t * t; s3 = fmaf(p, t, s3); px = fmaf(p, X, px);
            X = 0.5f * v.w; t = fmaxf(X - tau_f, 0.f); p = t * t; s3 = fmaf(p, t, s3); px = fmaf(p, X, px);
        }
        S3 = blockReduceSumAll(s3, sred);
        PX = blockReduceSumAll(px, sred);
    } else {
        // ---- Deterministic full-reference slow path (global reads) ----
        float tl = tau_lo0;
        float f_lo = relu2_pass(xr, d, tl, sred) - 1.0f;
        float dm2 = tau_hi0 - tl, tm = tl;
#pragma unroll 1
        for (int it = 0; it < 15; it++) {
            dm2 *= 0.5f;
            tm = tl + dm2;
            float fm = relu2_pass(xr, d, tm, sred) - 1.0f;
            tl = (fm * f_lo >= 0.f) ? tm : tl;
        }
        tau_f = tm;
        float s3 = 0.f, px = 0.f;
        for (int i = tid; i < d; i += NT) {
            float X = 0.5f * __ldg(xr + i);
            float t = fmaxf(X - tau_f, 0.f);
            float p = t * t;
            s3 = fmaf(p, t, s3);
            px = fmaf(p, X, px);
        }
        S3 = blockReduceSumAll(s3, sred);
        PX = blockReduceSumAll(px, sred);
    }

    if (tid == 0) {
        int t = load_target(tgt, row, n, d);
        float xt = __ldg(xr + t);
        // loss = (1 - S3)/(alpha*(alpha-1)) + sum(p*input) - input[target]
        //      = (1 - S3)/0.75 + 2*PX - xt        (input = 2*X)
        g_rowloss[row] = (1.0f - S3) / 0.75f + 2.0f * PX - xt;
    }
}

// Deterministic mean over rows
__global__ __launch_bounds__(1024) void reduce_kernel(float* __restrict__ out, int n) {
    __shared__ float sbuf[32];
    float s = 0.f;
    int n4 = n >> 2;
    const float4* p4 = (const float4*)g_rowloss;
    for (int i = threadIdx.x; i < n4; i += 1024) {
        float4 v = p4[i];
        s += (v.x + v.y) + (v.z + v.w);
    }
    for (int i = (n4 << 2) + threadIdx.x; i < n; i += 1024) s += g_rowloss[i];
    s = warpReduceSum(s);
    if ((threadIdx.x & 31) == 0) sbuf[threadIdx.x >> 5] = s;
    __syncthreads();
    if (threadIdx.x < 32) {
        float x = sbuf[threadIdx.x];
        x = warpReduceSum(x);
        if (threadIdx.x == 0) out[0] = x / (float)n;
    }
}

extern "C" void kernel_launch(void* const* d_in, const int* in_sizes, int n_in,
                              void* d_out, int out_size) {
    // Pick logits vs targets by size: the big buffer is the [n, d] logits.
    int idx_in = 0, idx_tg = 1;
    if (n_in >= 2 && in_sizes[1] > in_sizes[0]) { idx_in = 1; idx_tg = 0; }
    const float* in  = (const float*)d_in[idx_in];
    const void*  tgt = d_in[idx_tg];

    int n = in_sizes[idx_tg];
    if (n <= 0) n = 1;
    int d = in_sizes[idx_in] / n;
    if (n > MAXROWS) n = MAXROWS;   // shapes fixed: 4096 x 32000

    tsallis_kernel<<<n, NT>>>(in, tgt, d, n);
    reduce_kernel<<<1, 1024>>>((float*)d_out, n);
}